// round 16
// baseline (speedup 1.0000x reference)
#include <cuda_runtime.h>
#include <cstdint>

// FrozenBNBEmbedding: out[r, :] = code[ weight[token_r, :] ] * absmax[token_r]
// BLOCK (4096) == DIM (4096) -> per-row scalar scale absmax[token].
//
// Inputs (metadata order):
//   d_in[0] = input  : int32 [4, 2048]           token ids (8192)
//   d_in[1] = weight : int32 [50400, 4096]        int8 codes stored as int32
//   d_in[2] = absmax : float32 [n_blocks=50400]   per-block (== per-row) scale
//   d_in[3] = code   : float32 [256]              dequant LUT
// Output: float32 [4, 2048, 4096]

#ifndef DIM
#define DIM 4096
#endif

__global__ __launch_bounds__(256, 8)
void bnb_embed_kernel(const int* __restrict__ tokens,
                      const int* __restrict__ weight,
                      const float* __restrict__ absmax,
                      const float* __restrict__ code,
                      float* __restrict__ out,
                      int n_rows)
{
    __shared__ float s_code[256];
    const int tid = threadIdx.x;
    // Cooperative LUT load (blockDim.x == 256)
    s_code[tid] = __ldg(&code[tid]);
    __syncthreads();

    const int row = blockIdx.x;
    if (row >= n_rows) return;

    const int token = __ldg(&tokens[row]);
    const float scale = __ldg(&absmax[token]);

    const int4*  wrow = reinterpret_cast<const int4*>(weight + (size_t)token * DIM);
    float4*      orow = reinterpret_cast<float4*>(out + (size_t)row * DIM);

    // DIM/4 = 1024 int4 chunks; 256 threads -> 4 chunks/thread.
    // Front-batch the 4 global loads (MLP=4) to hide DRAM latency.
    int4 q0 = __ldg(&wrow[tid + 0 * 256]);
    int4 q1 = __ldg(&wrow[tid + 1 * 256]);
    int4 q2 = __ldg(&wrow[tid + 2 * 256]);
    int4 q3 = __ldg(&wrow[tid + 3 * 256]);

    float4 v;

    v.x = s_code[q0.x] * scale;
    v.y = s_code[q0.y] * scale;
    v.z = s_code[q0.z] * scale;
    v.w = s_code[q0.w] * scale;
    __stcs(&orow[tid + 0 * 256], v);   // streaming store: write-once, don't pollute L2

    v.x = s_code[q1.x] * scale;
    v.y = s_code[q1.y] * scale;
    v.z = s_code[q1.z] * scale;
    v.w = s_code[q1.w] * scale;
    __stcs(&orow[tid + 1 * 256], v);

    v.x = s_code[q2.x] * scale;
    v.y = s_code[q2.y] * scale;
    v.z = s_code[q2.z] * scale;
    v.w = s_code[q2.w] * scale;
    __stcs(&orow[tid + 2 * 256], v);

    v.x = s_code[q3.x] * scale;
    v.y = s_code[q3.y] * scale;
    v.z = s_code[q3.z] * scale;
    v.w = s_code[q3.w] * scale;
    __stcs(&orow[tid + 3 * 256], v);
}

extern "C" void kernel_launch(void* const* d_in, const int* in_sizes, int n_in,
                              void* d_out, int out_size)
{
    const int*   tokens = (const int*)d_in[0];
    const int*   weight = (const int*)d_in[1];
    const float* absmax = (const float*)d_in[2];
    const float* code   = (const float*)d_in[3];
    float*       out    = (float*)d_out;

    const int n_rows = in_sizes[0];   // 8192 tokens = output rows

    bnb_embed_kernel<<<n_rows, 256>>>(tokens, weight, absmax, code, out, n_rows);
}